// round 13
// baseline (speedup 1.0000x reference)
#include <cuda_runtime.h>

#define HH 224
#define WW 224
#define HW (HH * WW)
#define HW2 (HW / 2)
#define BB 256
#define NTOT (BB * HW)
#define DTc 0.15f
#define PIf 3.14159265358979f

#define TY 46                  // interior rows per tile
#define HALO 5                 // 5 fused steps per kernel
#define RR (TY + 2 * HALO)     // 56 data rows
#define RPAIRS (RR / 2)        // 28 vertical row-pair packs
#define RPP (RPAIRS + 2)       // +2 zero-pad pack rows -> 30
#define TCOLS 112              // thread-columns (each owns 2 pixel cols)
#define CW 114                 // cells per pack row incl 2 pads
#define TILES 5                // 5*46 = 230 >= 224
#define STRIPS 4
#define NTHREADS (TCOLS * STRIPS)    // 448; 2 CTAs/SM
#define PACKS_PER (RPAIRS / STRIPS)  // 7
#define SMP (RPP * CW)               // uint4 cells per buffer = 3420
#define SMEM_BYTES (2 * SMP * 16)    // 109440 B -> 2 CTAs/SM

typedef unsigned long long u64;
typedef unsigned int u32;

// Intermediate state between phases, fp16: per (batch, row, colpair) cell
// {s_h2 = (s_col2t, s_col2t+1), c_h2 = (c_col2t, c_col2t+1)}.
__device__ uint2 g_state[(long)BB * HW2];
// Per-tile omega-nonzero flag, published by phase-0 (pure function of input).
__device__ int g_tileflag[TILES];

// ---- packed f32x2 helpers ----
__device__ __forceinline__ u64 pk2(float lo, float hi) {
    u64 r; asm("mov.b64 %0, {%1, %2};" : "=l"(r) : "f"(lo), "f"(hi)); return r;
}
__device__ __forceinline__ void unpk2(u64 v, float& lo, float& hi) {
    asm("mov.b64 {%0, %1}, %2;" : "=f"(lo), "=f"(hi) : "l"(v));
}
__device__ __forceinline__ u64 mul2(u64 a, u64 b) {
    u64 d; asm("mul.rn.f32x2 %0, %1, %2;" : "=l"(d) : "l"(a), "l"(b)); return d;
}
__device__ __forceinline__ u64 fma2(u64 a, u64 b, u64 c) {
    u64 d; asm("fma.rn.f32x2 %0, %1, %2, %3;" : "=l"(d) : "l"(a), "l"(b), "l"(c)); return d;
}
__device__ __forceinline__ u64 neg2(u64 a) { return a ^ 0x8000000080000000ULL; }

// ---- fp16x2 helpers ----
__device__ __forceinline__ u32 hadd2(u32 a, u32 b) {
    u32 d; asm("add.rn.f16x2 %0, %1, %2;" : "=r"(d) : "r"(a), "r"(b)); return d;
}
// (a.hi16, b.lo16)
__device__ __forceinline__ u32 funnel16(u32 a, u32 b) {
    u32 d; asm("prmt.b32 %0, %1, %2, 0x5432;" : "=r"(d) : "r"(a), "r"(b)); return d;
}
// (a.lo16, b.lo16)
__device__ __forceinline__ u32 los16(u32 a, u32 b) {
    u32 d; asm("prmt.b32 %0, %1, %2, 0x5410;" : "=r"(d) : "r"(a), "r"(b)); return d;
}
// (a.hi16, b.hi16)
__device__ __forceinline__ u32 his16(u32 a, u32 b) {
    u32 d; asm("prmt.b32 %0, %1, %2, 0x7632;" : "=r"(d) : "r"(a), "r"(b)); return d;
}
__device__ __forceinline__ u64 h2f(u32 h) {
    float lo, hi;
    asm("{\n\t.reg .b16 l, h;\n\tmov.b32 {l, h}, %2;\n\t"
        "cvt.f32.f16 %0, l;\n\tcvt.f32.f16 %1, h;\n\t}"
        : "=f"(lo), "=f"(hi) : "r"(h));
    return pk2(lo, hi);
}
__device__ __forceinline__ u32 fpair2h(float lo, float hi) {
    u32 d; asm("cvt.rn.f16x2.f32 %0, %1, %2;" : "=r"(d) : "f"(hi), "f"(lo)); return d;
}
__device__ __forceinline__ u32 f2h(u64 v) {
    float lo, hi; unpk2(v, lo, hi); return fpair2h(lo, hi);
}

// 8-byte half-cell shared load: half=0 -> (x,y), half=8 -> (z,w).
__device__ __forceinline__ uint2 lds8(const uint4* buf, int cellIdx, int halfBytes) {
    return *(const uint2*)((const char*)(buf + cellIdx) + halfBytes);
}

struct SC { u64 DTK2, ONE2, C3, C2, C4; };

// Rotation core: cur sin/cos fp32x2, half2 neighbor sums, dto addend.
// |d| <= 0.3: sd = d(1 - d^2/6), cd = 1 - d^2/2 + d^4/24.
__device__ __forceinline__ void rot_core(u64 fs, u64 fc, u32 snh, u32 cnh,
                                         u64 dto, const SC& C,
                                         u64& os, u64& oc) {
    u64 sn = h2f(snh), cn = h2f(cnh);
    u64 m = neg2(fs);
    u64 coup = fma2(fc, sn, mul2(m, cn));
    u64 d = fma2(C.DTK2, coup, dto);
    u64 d2 = mul2(d, d);
    u64 sd = mul2(d, fma2(d2, C.C3, C.ONE2));
    u64 cd = fma2(d2, fma2(d2, C.C4, C.C2), C.ONE2);
    os = fma2(fs, cd, mul2(fc, sd));
    oc = fma2(fc, cd, mul2(m, sd));
}

template <int PHASE>  // 0: x_img -> g_state ; 1: g_state -> out
__global__ void __launch_bounds__(NTHREADS, 2)
fused5_kernel(const float* __restrict__ x_img,
              const float* __restrict__ omega,
              const float* __restrict__ Kp,
              float* __restrict__ out) {
    extern __shared__ uint4 sm4[];
    uint4* bufA = sm4;
    uint4* bufB = sm4 + SMP;

    const int tid = threadIdx.x;
    const int t = tid % TCOLS;         // owns pixel cols 2t, 2t+1
    const int strip = tid / TCOLS;
    const int r0p = 1 + strip * PACKS_PER;
    const int b = blockIdx.y;
    const int y0 = blockIdx.x * TY;
    const int xe = 2 * t;
    const int ic = t + 1;              // own cell within row
    const float2* __restrict__ om2 = (const float2*)omega;

    const float DTK = DTc * Kp[0];
    SC C;
    C.DTK2 = pk2(DTK, DTK);
    C.ONE2 = pk2(1.0f, 1.0f);
    C.C3 = pk2(-1.0f / 6.0f, -1.0f / 6.0f);
    C.C2 = pk2(-0.5f, -0.5f);
    C.C4 = pk2(4.1666668e-2f, 4.1666668e-2f);

    // Zero pad ring of both buffers (h2 zero bits = 0.0).
    const uint4 Z = make_uint4(0u, 0u, 0u, 0u);
    for (int i = tid; i < CW; i += NTHREADS) {
        bufA[i] = Z; bufA[(RPP - 1) * CW + i] = Z;
        bufB[i] = Z; bufB[(RPP - 1) * CW + i] = Z;
    }
    for (int r = 1 + tid; r < RPP - 1; r += NTHREADS) {
        bufA[r * CW] = Z; bufA[r * CW + CW - 1] = Z;
        bufB[r * CW] = Z; bufB[r * CW + CW - 1] = Z;
    }

    // Init state into bufA; out-of-image rows = exact 0.
    // Phase 0 also OR-reduces (its own omega cells != 0) -> per-tile flag.
    int acc = 0;
#pragma unroll
    for (int j = 0; j < PACKS_PER; j++) {
        const int rp = r0p + j;
        const int gy0 = y0 - HALO + 2 * (rp - 1);
        const int gy1 = gy0 + 1;
        const bool in0 = (gy0 >= 0) && (gy0 < HH);
        const bool in1 = (gy1 >= 0) && (gy1 < HH);
        if (PHASE == 0) {
            float sE0 = 0.f, cE0 = 0.f, sO0 = 0.f, cO0 = 0.f;
            float sE1 = 0.f, cE1 = 0.f, sO1 = 0.f, cO1 = 0.f;
            if (in0) {
                float2 v = *(const float2*)&x_img[b * HW + gy0 * WW + xe];
                __sincosf(fmaf(2.0f * PIf, v.x, -PIf), &sE0, &cE0);
                __sincosf(fmaf(2.0f * PIf, v.y, -PIf), &sO0, &cO0);
                float2 o = om2[gy0 * TCOLS + t];
                acc |= (o.x != 0.f) | (o.y != 0.f);
            }
            if (in1) {
                float2 v = *(const float2*)&x_img[b * HW + gy1 * WW + xe];
                __sincosf(fmaf(2.0f * PIf, v.x, -PIf), &sE1, &cE1);
                __sincosf(fmaf(2.0f * PIf, v.y, -PIf), &sO1, &cO1);
                float2 o = om2[gy1 * TCOLS + t];
                acc |= (o.x != 0.f) | (o.y != 0.f);
            }
            bufA[rp * CW + ic] = make_uint4(fpair2h(sE0, sE1), fpair2h(cE0, cE1),
                                            fpair2h(sO0, sO1), fpair2h(cO0, cO1));
        } else {
            // fp16 in, fp16 cells out: pure PRMT repack, zero conversions.
            uint2 v0 = in0 ? g_state[(long)b * HW2 + gy0 * TCOLS + t] : make_uint2(0u, 0u);
            uint2 v1 = in1 ? g_state[(long)b * HW2 + gy1 * TCOLS + t] : make_uint2(0u, 0u);
            bufA[rp * CW + ic] = make_uint4(los16(v0.x, v1.x), los16(v0.y, v1.y),
                                            his16(v0.x, v1.x), his16(v0.y, v1.y));
        }
    }

    // Flag: phase 0 computes per-CTA (covers exactly the omega cells it uses)
    // and publishes per-tile; phase 1 reads the published value. The OR doubles
    // as the post-init barrier.
    int flg;
    if (PHASE == 0) {
        flg = __syncthreads_or(acc);
        if (b == 0 && tid == 0) g_tileflag[blockIdx.x] = flg;
    } else {
        flg = g_tileflag[blockIdx.x];
        __syncthreads();
    }

    const int gybase = y0 - HALO + 2 * (r0p - 1);
    const uint4* p = bufA;
    uint4* q = bufB;

    // Steps 1..HALO-1: smem -> smem (fp16), software-pipelined loads.
#pragma unroll 1
    for (int st = 0; st < HALO - 1; st++) {
        int idx = r0p * CW + ic;
        uint4 t4 = p[idx - CW];
        uint4 c4 = p[idx];
        u32 uEs = hadd2(t4.x, c4.x), uEc = hadd2(t4.y, c4.y);
        u32 uOs = hadd2(t4.z, c4.z), uOc = hadd2(t4.w, c4.w);
        u64 fEs = h2f(c4.x), fEc = h2f(c4.y);
        u64 fOs = h2f(c4.z), fOc = h2f(c4.w);
        // Prologue loads for iter 0.
        uint4 n4 = p[idx + CW];
        uint2 lf = lds8(p, idx - 1, 8);   // left cell O-half: (sO, cO) of col 2t-1
        uint2 rg = lds8(p, idx + 1, 0);   // right cell E-half: (sE, cE) of col 2t+2
#pragma unroll
        for (int j = 0; j < PACKS_PER; j++) {
            // Prefetch next iteration's loads ahead of this iteration's compute.
            uint4 n42; uint2 lf2, rg2;
            if (j < PACKS_PER - 1) {
                n42 = p[idx + 2 * CW];
                lf2 = lds8(p, idx + CW - 1, 8);
                rg2 = lds8(p, idx + CW + 1, 0);
            }

            u32 vEs = hadd2(c4.x, n4.x), vEc = hadd2(c4.y, n4.y);
            u32 vOs = hadd2(c4.z, n4.z), vOc = hadd2(c4.w, n4.w);
            u32 snE = hadd2(funnel16(uEs, vEs), hadd2(lf.x, c4.z));
            u32 cnE = hadd2(funnel16(uEc, vEc), hadd2(lf.y, c4.w));
            u32 snO = hadd2(funnel16(uOs, vOs), hadd2(c4.x, rg.x));
            u32 cnO = hadd2(funnel16(uOc, vOc), hadd2(c4.y, rg.y));

            u64 dtoE = 0, dtoO = 0;
            if (flg) {   // uniform branch; omega==0 fast path skips
                const int gy0 = gybase + 2 * j, gy1 = gy0 + 1;
                float2 o0 = (gy0 >= 0 && gy0 < HH) ? om2[gy0 * TCOLS + t] : make_float2(0.f, 0.f);
                float2 o1 = (gy1 >= 0 && gy1 < HH) ? om2[gy1 * TCOLS + t] : make_float2(0.f, 0.f);
                dtoE = pk2(DTc * o0.x, DTc * o1.x);
                dtoO = pk2(DTc * o0.y, DTc * o1.y);
            }

            u64 osE, ocE, osO, ocO;
            rot_core(fEs, fEc, snE, cnE, dtoE, C, osE, ocE);
            rot_core(fOs, fOc, snO, cnO, dtoO, C, osO, ocO);
            q[idx] = make_uint4(f2h(osE), f2h(ocE), f2h(osO), f2h(ocO));

            uEs = vEs; uEc = vEc; uOs = vOs; uOc = vOc;
            c4 = n4;
            fEs = h2f(n4.x); fEc = h2f(n4.y);
            fOs = h2f(n4.z); fOc = h2f(n4.w);
            n4 = n42; lf = lf2; rg = rg2;
            idx += CW;
        }
        __syncthreads();
        const uint4* tp = q;
        q = (uint4*)p;
        p = tp;
    }

    // Final step: compute fp32, write interior rows straight to global.
    {
        int idx = r0p * CW + ic;
        uint4 t4 = p[idx - CW];
        uint4 c4 = p[idx];
        u32 uEs = hadd2(t4.x, c4.x), uEc = hadd2(t4.y, c4.y);
        u32 uOs = hadd2(t4.z, c4.z), uOc = hadd2(t4.w, c4.w);
        u64 fEs = h2f(c4.x), fEc = h2f(c4.y);
        u64 fOs = h2f(c4.z), fOc = h2f(c4.w);
        uint4 n4 = p[idx + CW];
        uint2 lf = lds8(p, idx - 1, 8);
        uint2 rg = lds8(p, idx + 1, 0);
#pragma unroll
        for (int j = 0; j < PACKS_PER; j++) {
            uint4 n42; uint2 lf2, rg2;
            if (j < PACKS_PER - 1) {
                n42 = p[idx + 2 * CW];
                lf2 = lds8(p, idx + CW - 1, 8);
                rg2 = lds8(p, idx + CW + 1, 0);
            }

            u32 vEs = hadd2(c4.x, n4.x), vEc = hadd2(c4.y, n4.y);
            u32 vOs = hadd2(c4.z, n4.z), vOc = hadd2(c4.w, n4.w);
            u32 snE = hadd2(funnel16(uEs, vEs), hadd2(lf.x, c4.z));
            u32 cnE = hadd2(funnel16(uEc, vEc), hadd2(lf.y, c4.w));
            u32 snO = hadd2(funnel16(uOs, vOs), hadd2(c4.x, rg.x));
            u32 cnO = hadd2(funnel16(uOc, vOc), hadd2(c4.y, rg.y));

            u64 dtoE = 0, dtoO = 0;
            if (flg) {
                const int gy0 = gybase + 2 * j, gy1 = gy0 + 1;
                float2 o0 = (gy0 >= 0 && gy0 < HH) ? om2[gy0 * TCOLS + t] : make_float2(0.f, 0.f);
                float2 o1 = (gy1 >= 0 && gy1 < HH) ? om2[gy1 * TCOLS + t] : make_float2(0.f, 0.f);
                dtoE = pk2(DTc * o0.x, DTc * o1.x);
                dtoO = pk2(DTc * o0.y, DTc * o1.y);
            }

            u64 osE, ocE, osO, ocO;
            rot_core(fEs, fEc, snE, cnE, dtoE, C, osE, ocE);
            rot_core(fOs, fOc, snO, cnO, dtoO, C, osO, ocO);

            float se0, se1, ce0, ce1, so0, so1, co0, co1;
            unpk2(osE, se0, se1); unpk2(ocE, ce0, ce1);
            unpk2(osO, so0, so1); unpk2(ocO, co0, co1);
            const int rt0 = 2 * (r0p + j - 1);
#pragma unroll
            for (int par = 0; par < 2; par++) {
                const int rt = rt0 + par;
                if (rt >= HALO && rt < HALO + TY) {
                    const int gy = y0 + (rt - HALO);
                    if (gy < HH) {
                        float ws0 = par ? se1 : se0;   // s col 2t
                        float ws1 = par ? so1 : so0;   // s col 2t+1
                        float wc0 = par ? ce1 : ce0;   // c col 2t
                        float wc1 = par ? co1 : co0;   // c col 2t+1
                        if (PHASE == 0) {
                            g_state[(long)b * HW2 + gy * TCOLS + t] =
                                make_uint2(fpair2h(ws0, ws1), fpair2h(wc0, wc1));
                        } else {
                            const int pix = gy * WW + xe;
                            *(float2*)&out[(long)b * (2 * HW) + pix] = make_float2(wc0, wc1);
                            *(float2*)&out[(long)b * (2 * HW) + HW + pix] = make_float2(ws0, ws1);
                        }
                    }
                }
            }

            uEs = vEs; uEc = vEc; uOs = vOs; uOc = vOc;
            c4 = n4;
            fEs = h2f(n4.x); fEc = h2f(n4.y);
            fOs = h2f(n4.z); fOc = h2f(n4.w);
            n4 = n42; lf = lf2; rg = rg2;
            idx += CW;
        }
    }
}

extern "C" void kernel_launch(void* const* d_in, const int* in_sizes, int n_in,
                              void* d_out, int out_size) {
    const float* x_img = (const float*)d_in[0];  // (B,1,H,W)
    const float* omega = (const float*)d_in[1];  // (1,1,H,W)
    const float* Kp    = (const float*)d_in[2];  // scalar
    float* out = (float*)d_out;

    static bool configured = false;
    if (!configured) {
        cudaFuncSetAttribute(fused5_kernel<0>,
                             cudaFuncAttributeMaxDynamicSharedMemorySize, SMEM_BYTES);
        cudaFuncSetAttribute(fused5_kernel<1>,
                             cudaFuncAttributeMaxDynamicSharedMemorySize, SMEM_BYTES);
        configured = true;
    }

    dim3 grid(TILES, BB);
    dim3 block(NTHREADS);
    fused5_kernel<0><<<grid, block, SMEM_BYTES>>>(x_img, omega, Kp, out);
    fused5_kernel<1><<<grid, block, SMEM_BYTES>>>(x_img, omega, Kp, out);
}

// round 14
// speedup vs baseline: 1.0743x; 1.0743x over previous
#include <cuda_runtime.h>

#define HH 224
#define WW 224
#define HW (HH * WW)
#define HW2 (HW / 2)
#define BB 256
#define NTOT (BB * HW)
#define DTc 0.15f
#define PIf 3.14159265358979f

#define TY 46                  // interior rows per tile
#define HALO 5                 // 5 fused steps per kernel
#define RR (TY + 2 * HALO)     // 56 data rows
#define RPAIRS (RR / 2)        // 28 vertical row-pair packs
#define RPP (RPAIRS + 2)       // +2 zero-pad pack rows -> 30
#define TCOLS 112              // thread-columns (each owns 2 pixel cols)
#define CW 114                 // cells per pack row incl 2 pads
#define TILES 5                // 5*46 = 230 >= 224
#define STRIPS 4
#define NTHREADS (TCOLS * STRIPS)    // 448; 2 CTAs/SM
#define PACKS_PER (RPAIRS / STRIPS)  // 7
#define SMP (RPP * CW)               // uint4 cells per buffer = 3420
#define SMEM_BYTES (2 * SMP * 16)    // 109440 B -> 2 CTAs/SM

typedef unsigned long long u64;
typedef unsigned int u32;

// Intermediate state between phases, fp16: per (batch, row, colpair) cell
// {s_h2 = (s_col2t, s_col2t+1), c_h2 = (c_col2t, c_col2t+1)}.
__device__ uint2 g_state[(long)BB * HW2];
__device__ int g_parts[64];     // partial omega-nonzero flags

// ---- packed f32x2 helpers ----
__device__ __forceinline__ u64 pk2(float lo, float hi) {
    u64 r; asm("mov.b64 %0, {%1, %2};" : "=l"(r) : "f"(lo), "f"(hi)); return r;
}
__device__ __forceinline__ void unpk2(u64 v, float& lo, float& hi) {
    asm("mov.b64 {%0, %1}, %2;" : "=f"(lo), "=f"(hi) : "l"(v));
}
__device__ __forceinline__ u64 mul2(u64 a, u64 b) {
    u64 d; asm("mul.rn.f32x2 %0, %1, %2;" : "=l"(d) : "l"(a), "l"(b)); return d;
}
__device__ __forceinline__ u64 fma2(u64 a, u64 b, u64 c) {
    u64 d; asm("fma.rn.f32x2 %0, %1, %2, %3;" : "=l"(d) : "l"(a), "l"(b), "l"(c)); return d;
}
__device__ __forceinline__ u64 neg2(u64 a) { return a ^ 0x8000000080000000ULL; }

// ---- fp16x2 helpers ----
__device__ __forceinline__ u32 hadd2(u32 a, u32 b) {
    u32 d; asm("add.rn.f16x2 %0, %1, %2;" : "=r"(d) : "r"(a), "r"(b)); return d;
}
__device__ __forceinline__ u32 hmul2(u32 a, u32 b) {
    u32 d; asm("mul.rn.f16x2 %0, %1, %2;" : "=r"(d) : "r"(a), "r"(b)); return d;
}
__device__ __forceinline__ u32 hfma2(u32 a, u32 b, u32 c) {
    u32 d; asm("fma.rn.f16x2 %0, %1, %2, %3;" : "=r"(d) : "r"(a), "r"(b), "r"(c)); return d;
}
__device__ __forceinline__ u32 hneg2(u32 a) { return a ^ 0x80008000u; }
// (a.hi16, b.lo16)
__device__ __forceinline__ u32 funnel16(u32 a, u32 b) {
    u32 d; asm("prmt.b32 %0, %1, %2, 0x5432;" : "=r"(d) : "r"(a), "r"(b)); return d;
}
// (a.lo16, b.lo16)
__device__ __forceinline__ u32 los16(u32 a, u32 b) {
    u32 d; asm("prmt.b32 %0, %1, %2, 0x5410;" : "=r"(d) : "r"(a), "r"(b)); return d;
}
// (a.hi16, b.hi16)
__device__ __forceinline__ u32 his16(u32 a, u32 b) {
    u32 d; asm("prmt.b32 %0, %1, %2, 0x7632;" : "=r"(d) : "r"(a), "r"(b)); return d;
}
__device__ __forceinline__ u64 h2f(u32 h) {
    float lo, hi;
    asm("{\n\t.reg .b16 l, h;\n\tmov.b32 {l, h}, %2;\n\t"
        "cvt.f32.f16 %0, l;\n\tcvt.f32.f16 %1, h;\n\t}"
        : "=f"(lo), "=f"(hi) : "r"(h));
    return pk2(lo, hi);
}
__device__ __forceinline__ u32 fpair2h(float lo, float hi) {
    u32 d; asm("cvt.rn.f16x2.f32 %0, %1, %2;" : "=r"(d) : "f"(hi), "f"(lo)); return d;
}
__device__ __forceinline__ u32 f2h(u64 v) {
    float lo, hi; unpk2(v, lo, hi); return fpair2h(lo, hi);
}

// 8-byte half-cell shared load: half=0 -> (x,y), half=8 -> (z,w).
__device__ __forceinline__ uint2 lds8(const uint4* buf, int cellIdx, int halfBytes) {
    return *(const uint2*)((const char*)(buf + cellIdx) + halfBytes);
}

struct SC { u64 DTK2, ONE2, C3, C2, C4; };

// Rotation core. Coupling computed natively in fp16 from the fp16 center
// (fsh, fch) and fp16 neighbor sums -> one h2f instead of two.
// |d| <= 0.3: sd = d(1 - d^2/6), cd = 1 - d^2/2 + d^4/24.
__device__ __forceinline__ void rot_core(u32 fsh, u32 fch, u64 fs, u64 fc,
                                         u32 snh, u32 cnh,
                                         u64 dto, const SC& C,
                                         u64& os, u64& oc) {
    u32 coup_h = hfma2(fch, snh, hneg2(hmul2(fsh, cnh)));   // fc*sn - fs*cn (fp16)
    u64 d = fma2(C.DTK2, h2f(coup_h), dto);
    u64 d2 = mul2(d, d);
    u64 sd = mul2(d, fma2(d2, C.C3, C.ONE2));
    u64 cd = fma2(d2, fma2(d2, C.C4, C.C2), C.ONE2);
    u64 m = neg2(fs);
    os = fma2(fs, cd, mul2(fc, sd));
    oc = fma2(fc, cd, mul2(m, sd));
}

// 64-block partial OR of (omega != 0). Pure function of input -> deterministic.
__global__ void __launch_bounds__(256) flag_kernel(const float* __restrict__ om) {
    const float4* om4 = (const float4*)om;
    int acc = 0;
    for (int i = blockIdx.x * 256 + threadIdx.x; i < HW / 4; i += 64 * 256) {
        float4 v = om4[i];
        acc |= (v.x != 0.f) | (v.y != 0.f) | (v.z != 0.f) | (v.w != 0.f);
    }
    int any = __syncthreads_or(acc);
    if (threadIdx.x == 0) g_parts[blockIdx.x] = any;
}

template <int PHASE>  // 0: x_img -> g_state ; 1: g_state -> out
__global__ void __launch_bounds__(NTHREADS, 2)
fused5_kernel(const float* __restrict__ x_img,
              const float* __restrict__ omega,
              const float* __restrict__ Kp,
              float* __restrict__ out) {
    extern __shared__ uint4 sm4[];
    uint4* bufA = sm4;
    uint4* bufB = sm4 + SMP;

    const int tid = threadIdx.x;
    const int t = tid % TCOLS;         // owns pixel cols 2t, 2t+1
    const int strip = tid / TCOLS;
    const int r0p = 1 + strip * PACKS_PER;
    const int b = blockIdx.y;
    const int y0 = blockIdx.x * TY;
    const int xe = 2 * t;
    const int ic = t + 1;              // own cell within row
    const float2* __restrict__ om2 = (const float2*)omega;

    const float DTK = DTc * Kp[0];
    SC C;
    C.DTK2 = pk2(DTK, DTK);
    C.ONE2 = pk2(1.0f, 1.0f);
    C.C3 = pk2(-1.0f / 6.0f, -1.0f / 6.0f);
    C.C2 = pk2(-0.5f, -0.5f);
    C.C4 = pk2(4.1666668e-2f, 4.1666668e-2f);

    // Zero pad ring of both buffers (h2 zero bits = 0.0).
    const uint4 Z = make_uint4(0u, 0u, 0u, 0u);
    for (int i = tid; i < CW; i += NTHREADS) {
        bufA[i] = Z; bufA[(RPP - 1) * CW + i] = Z;
        bufB[i] = Z; bufB[(RPP - 1) * CW + i] = Z;
    }
    for (int r = 1 + tid; r < RPP - 1; r += NTHREADS) {
        bufA[r * CW] = Z; bufA[r * CW + CW - 1] = Z;
        bufB[r * CW] = Z; bufB[r * CW + CW - 1] = Z;
    }

    // Init state into bufA; out-of-image rows = exact 0.
#pragma unroll
    for (int j = 0; j < PACKS_PER; j++) {
        const int rp = r0p + j;
        const int gy0 = y0 - HALO + 2 * (rp - 1);
        const int gy1 = gy0 + 1;
        const bool in0 = (gy0 >= 0) && (gy0 < HH);
        const bool in1 = (gy1 >= 0) && (gy1 < HH);
        if (PHASE == 0) {
            float sE0 = 0.f, cE0 = 0.f, sO0 = 0.f, cO0 = 0.f;
            float sE1 = 0.f, cE1 = 0.f, sO1 = 0.f, cO1 = 0.f;
            if (in0) {
                float2 v = *(const float2*)&x_img[b * HW + gy0 * WW + xe];
                __sincosf(fmaf(2.0f * PIf, v.x, -PIf), &sE0, &cE0);
                __sincosf(fmaf(2.0f * PIf, v.y, -PIf), &sO0, &cO0);
            }
            if (in1) {
                float2 v = *(const float2*)&x_img[b * HW + gy1 * WW + xe];
                __sincosf(fmaf(2.0f * PIf, v.x, -PIf), &sE1, &cE1);
                __sincosf(fmaf(2.0f * PIf, v.y, -PIf), &sO1, &cO1);
            }
            bufA[rp * CW + ic] = make_uint4(fpair2h(sE0, sE1), fpair2h(cE0, cE1),
                                            fpair2h(sO0, sO1), fpair2h(cO0, cO1));
        } else {
            // fp16 in, fp16 cells out: pure PRMT repack, zero conversions.
            uint2 v0 = in0 ? g_state[(long)b * HW2 + gy0 * TCOLS + t] : make_uint2(0u, 0u);
            uint2 v1 = in1 ? g_state[(long)b * HW2 + gy1 * TCOLS + t] : make_uint2(0u, 0u);
            bufA[rp * CW + ic] = make_uint4(los16(v0.x, v1.x), los16(v0.y, v1.y),
                                            his16(v0.x, v1.x), his16(v0.y, v1.y));
        }
    }

    // Fold the omega flag (doubles as the post-init barrier).
    int pf = (tid < 64) ? g_parts[tid] : 0;
    const int flg = __syncthreads_or(pf);

    const int gybase = y0 - HALO + 2 * (r0p - 1);
    const uint4* p = bufA;
    uint4* q = bufB;

    // Steps 1..HALO-1: smem -> smem (fp16), software-pipelined loads.
#pragma unroll 1
    for (int st = 0; st < HALO - 1; st++) {
        int idx = r0p * CW + ic;
        uint4 t4 = p[idx - CW];
        uint4 c4 = p[idx];
        u32 uEs = hadd2(t4.x, c4.x), uEc = hadd2(t4.y, c4.y);
        u32 uOs = hadd2(t4.z, c4.z), uOc = hadd2(t4.w, c4.w);
        u64 fEs = h2f(c4.x), fEc = h2f(c4.y);
        u64 fOs = h2f(c4.z), fOc = h2f(c4.w);
        // Prologue loads for iter 0.
        uint4 n4 = p[idx + CW];
        uint2 lf = lds8(p, idx - 1, 8);   // left cell O-half: (sO, cO) of col 2t-1
        uint2 rg = lds8(p, idx + 1, 0);   // right cell E-half: (sE, cE) of col 2t+2
#pragma unroll
        for (int j = 0; j < PACKS_PER; j++) {
            // Prefetch next iteration's loads ahead of this iteration's compute.
            uint4 n42; uint2 lf2, rg2;
            if (j < PACKS_PER - 1) {
                n42 = p[idx + 2 * CW];
                lf2 = lds8(p, idx + CW - 1, 8);
                rg2 = lds8(p, idx + CW + 1, 0);
            }

            u32 vEs = hadd2(c4.x, n4.x), vEc = hadd2(c4.y, n4.y);
            u32 vOs = hadd2(c4.z, n4.z), vOc = hadd2(c4.w, n4.w);
            u32 snE = hadd2(funnel16(uEs, vEs), hadd2(lf.x, c4.z));
            u32 cnE = hadd2(funnel16(uEc, vEc), hadd2(lf.y, c4.w));
            u32 snO = hadd2(funnel16(uOs, vOs), hadd2(c4.x, rg.x));
            u32 cnO = hadd2(funnel16(uOc, vOc), hadd2(c4.y, rg.y));

            u64 dtoE = 0, dtoO = 0;
            if (flg) {   // uniform branch; omega==0 fast path skips
                const int gy0 = gybase + 2 * j, gy1 = gy0 + 1;
                float2 o0 = (gy0 >= 0 && gy0 < HH) ? om2[gy0 * TCOLS + t] : make_float2(0.f, 0.f);
                float2 o1 = (gy1 >= 0 && gy1 < HH) ? om2[gy1 * TCOLS + t] : make_float2(0.f, 0.f);
                dtoE = pk2(DTc * o0.x, DTc * o1.x);
                dtoO = pk2(DTc * o0.y, DTc * o1.y);
            }

            u64 osE, ocE, osO, ocO;
            rot_core(c4.x, c4.y, fEs, fEc, snE, cnE, dtoE, C, osE, ocE);
            rot_core(c4.z, c4.w, fOs, fOc, snO, cnO, dtoO, C, osO, ocO);
            q[idx] = make_uint4(f2h(osE), f2h(ocE), f2h(osO), f2h(ocO));

            uEs = vEs; uEc = vEc; uOs = vOs; uOc = vOc;
            c4 = n4;
            fEs = h2f(n4.x); fEc = h2f(n4.y);
            fOs = h2f(n4.z); fOc = h2f(n4.w);
            n4 = n42; lf = lf2; rg = rg2;
            idx += CW;
        }
        __syncthreads();
        const uint4* tp = q;
        q = (uint4*)p;
        p = tp;
    }

    // Final step: compute fp32, write interior rows straight to global.
    {
        int idx = r0p * CW + ic;
        uint4 t4 = p[idx - CW];
        uint4 c4 = p[idx];
        u32 uEs = hadd2(t4.x, c4.x), uEc = hadd2(t4.y, c4.y);
        u32 uOs = hadd2(t4.z, c4.z), uOc = hadd2(t4.w, c4.w);
        u64 fEs = h2f(c4.x), fEc = h2f(c4.y);
        u64 fOs = h2f(c4.z), fOc = h2f(c4.w);
        uint4 n4 = p[idx + CW];
        uint2 lf = lds8(p, idx - 1, 8);
        uint2 rg = lds8(p, idx + 1, 0);
#pragma unroll
        for (int j = 0; j < PACKS_PER; j++) {
            uint4 n42; uint2 lf2, rg2;
            if (j < PACKS_PER - 1) {
                n42 = p[idx + 2 * CW];
                lf2 = lds8(p, idx + CW - 1, 8);
                rg2 = lds8(p, idx + CW + 1, 0);
            }

            u32 vEs = hadd2(c4.x, n4.x), vEc = hadd2(c4.y, n4.y);
            u32 vOs = hadd2(c4.z, n4.z), vOc = hadd2(c4.w, n4.w);
            u32 snE = hadd2(funnel16(uEs, vEs), hadd2(lf.x, c4.z));
            u32 cnE = hadd2(funnel16(uEc, vEc), hadd2(lf.y, c4.w));
            u32 snO = hadd2(funnel16(uOs, vOs), hadd2(c4.x, rg.x));
            u32 cnO = hadd2(funnel16(uOc, vOc), hadd2(c4.y, rg.y));

            u64 dtoE = 0, dtoO = 0;
            if (flg) {
                const int gy0 = gybase + 2 * j, gy1 = gy0 + 1;
                float2 o0 = (gy0 >= 0 && gy0 < HH) ? om2[gy0 * TCOLS + t] : make_float2(0.f, 0.f);
                float2 o1 = (gy1 >= 0 && gy1 < HH) ? om2[gy1 * TCOLS + t] : make_float2(0.f, 0.f);
                dtoE = pk2(DTc * o0.x, DTc * o1.x);
                dtoO = pk2(DTc * o0.y, DTc * o1.y);
            }

            u64 osE, ocE, osO, ocO;
            rot_core(c4.x, c4.y, fEs, fEc, snE, cnE, dtoE, C, osE, ocE);
            rot_core(c4.z, c4.w, fOs, fOc, snO, cnO, dtoO, C, osO, ocO);

            float se0, se1, ce0, ce1, so0, so1, co0, co1;
            unpk2(osE, se0, se1); unpk2(ocE, ce0, ce1);
            unpk2(osO, so0, so1); unpk2(ocO, co0, co1);
            const int rt0 = 2 * (r0p + j - 1);
#pragma unroll
            for (int par = 0; par < 2; par++) {
                const int rt = rt0 + par;
                if (rt >= HALO && rt < HALO + TY) {
                    const int gy = y0 + (rt - HALO);
                    if (gy < HH) {
                        float ws0 = par ? se1 : se0;   // s col 2t
                        float ws1 = par ? so1 : so0;   // s col 2t+1
                        float wc0 = par ? ce1 : ce0;   // c col 2t
                        float wc1 = par ? co1 : co0;   // c col 2t+1
                        if (PHASE == 0) {
                            g_state[(long)b * HW2 + gy * TCOLS + t] =
                                make_uint2(fpair2h(ws0, ws1), fpair2h(wc0, wc1));
                        } else {
                            const int pix = gy * WW + xe;
                            *(float2*)&out[(long)b * (2 * HW) + pix] = make_float2(wc0, wc1);
                            *(float2*)&out[(long)b * (2 * HW) + HW + pix] = make_float2(ws0, ws1);
                        }
                    }
                }
            }

            uEs = vEs; uEc = vEc; uOs = vOs; uOc = vOc;
            c4 = n4;
            fEs = h2f(n4.x); fEc = h2f(n4.y);
            fOs = h2f(n4.z); fOc = h2f(n4.w);
            n4 = n42; lf = lf2; rg = rg2;
            idx += CW;
        }
    }
}

extern "C" void kernel_launch(void* const* d_in, const int* in_sizes, int n_in,
                              void* d_out, int out_size) {
    const float* x_img = (const float*)d_in[0];  // (B,1,H,W)
    const float* omega = (const float*)d_in[1];  // (1,1,H,W)
    const float* Kp    = (const float*)d_in[2];  // scalar
    float* out = (float*)d_out;

    static bool configured = false;
    if (!configured) {
        cudaFuncSetAttribute(fused5_kernel<0>,
                             cudaFuncAttributeMaxDynamicSharedMemorySize, SMEM_BYTES);
        cudaFuncSetAttribute(fused5_kernel<1>,
                             cudaFuncAttributeMaxDynamicSharedMemorySize, SMEM_BYTES);
        configured = true;
    }

    flag_kernel<<<64, 256>>>(omega);

    dim3 grid(TILES, BB);
    dim3 block(NTHREADS);
    fused5_kernel<0><<<grid, block, SMEM_BYTES>>>(x_img, omega, Kp, out);
    fused5_kernel<1><<<grid, block, SMEM_BYTES>>>(x_img, omega, Kp, out);
}

// round 15
// speedup vs baseline: 1.1902x; 1.1079x over previous
#include <cuda_runtime.h>

#define HH 224
#define WW 224
#define HW (HH * WW)
#define HW2 (HW / 2)
#define BB 256
#define NTOT (BB * HW)
#define DTc 0.15f
#define PIf 3.14159265358979f

#define TY 46                  // interior rows per tile
#define HALO 5                 // 5 fused steps per kernel
#define RR (TY + 2 * HALO)     // 56 data rows
#define RPAIRS (RR / 2)        // 28 vertical row-pair packs
#define RPP (RPAIRS + 2)       // +2 zero-pad pack rows -> 30
#define TCOLS 112              // thread-columns (each owns 2 pixel cols)
#define CW 114                 // cells per pack row incl 2 pads
#define TILES 5                // 5*46 = 230 >= 224
#define STRIPS 4
#define NTHREADS (TCOLS * STRIPS)    // 448; 2 CTAs/SM
#define PACKS_PER (RPAIRS / STRIPS)  // 7
#define SMP (RPP * CW)               // uint4 cells per buffer = 3420
#define SMEM_BYTES (2 * SMP * 16)    // 109440 B -> 2 CTAs/SM

typedef unsigned long long u64;
typedef unsigned int u32;

// Intermediate state between phases, fp16: per (batch, row, colpair) cell
// {s_h2 = (s_col2t, s_col2t+1), c_h2 = (c_col2t, c_col2t+1)}.
__device__ uint2 g_state[(long)BB * HW2];
__device__ int g_parts[64];     // partial omega-nonzero flags

// ---- packed f32x2 helpers ----
__device__ __forceinline__ u64 pk2(float lo, float hi) {
    u64 r; asm("mov.b64 %0, {%1, %2};" : "=l"(r) : "f"(lo), "f"(hi)); return r;
}
__device__ __forceinline__ void unpk2(u64 v, float& lo, float& hi) {
    asm("mov.b64 {%0, %1}, %2;" : "=f"(lo), "=f"(hi) : "l"(v));
}
__device__ __forceinline__ u64 mul2(u64 a, u64 b) {
    u64 d; asm("mul.rn.f32x2 %0, %1, %2;" : "=l"(d) : "l"(a), "l"(b)); return d;
}
__device__ __forceinline__ u64 fma2(u64 a, u64 b, u64 c) {
    u64 d; asm("fma.rn.f32x2 %0, %1, %2, %3;" : "=l"(d) : "l"(a), "l"(b), "l"(c)); return d;
}
__device__ __forceinline__ u64 neg2(u64 a) { return a ^ 0x8000000080000000ULL; }

// ---- fp16x2 helpers ----
__device__ __forceinline__ u32 hadd2(u32 a, u32 b) {
    u32 d; asm("add.rn.f16x2 %0, %1, %2;" : "=r"(d) : "r"(a), "r"(b)); return d;
}
__device__ __forceinline__ u32 hmul2(u32 a, u32 b) {
    u32 d; asm("mul.rn.f16x2 %0, %1, %2;" : "=r"(d) : "r"(a), "r"(b)); return d;
}
__device__ __forceinline__ u32 hfma2(u32 a, u32 b, u32 c) {
    u32 d; asm("fma.rn.f16x2 %0, %1, %2, %3;" : "=r"(d) : "r"(a), "r"(b), "r"(c)); return d;
}
__device__ __forceinline__ u32 hneg2(u32 a) { return a ^ 0x80008000u; }
// (a.hi16, b.lo16)
__device__ __forceinline__ u32 funnel16(u32 a, u32 b) {
    u32 d; asm("prmt.b32 %0, %1, %2, 0x5432;" : "=r"(d) : "r"(a), "r"(b)); return d;
}
// (a.lo16, b.lo16)
__device__ __forceinline__ u32 los16(u32 a, u32 b) {
    u32 d; asm("prmt.b32 %0, %1, %2, 0x5410;" : "=r"(d) : "r"(a), "r"(b)); return d;
}
// (a.hi16, b.hi16)
__device__ __forceinline__ u32 his16(u32 a, u32 b) {
    u32 d; asm("prmt.b32 %0, %1, %2, 0x7632;" : "=r"(d) : "r"(a), "r"(b)); return d;
}
__device__ __forceinline__ u64 h2f(u32 h) {
    float lo, hi;
    asm("{\n\t.reg .b16 l, h;\n\tmov.b32 {l, h}, %2;\n\t"
        "cvt.f32.f16 %0, l;\n\tcvt.f32.f16 %1, h;\n\t}"
        : "=f"(lo), "=f"(hi) : "r"(h));
    return pk2(lo, hi);
}
__device__ __forceinline__ u32 fpair2h(float lo, float hi) {
    u32 d; asm("cvt.rn.f16x2.f32 %0, %1, %2;" : "=r"(d) : "f"(hi), "f"(lo)); return d;
}
__device__ __forceinline__ u32 f2h(u64 v) {
    float lo, hi; unpk2(v, lo, hi); return fpair2h(lo, hi);
}

// 8-byte half-cell shared load: half=0 -> (x,y), half=8 -> (z,w).
__device__ __forceinline__ uint2 lds8(const uint4* buf, int cellIdx, int halfBytes) {
    return *(const uint2*)((const char*)(buf + cellIdx) + halfBytes);
}

struct SC { u64 DTK2, ONE2, C3, C2, C4; };
struct SCH { u32 DTKh, ONEh, C3h, mHh, C24h; };  // fp16x2 constants

// Middle-step rotation, 100% fp16 (delta form):
//   d   = DTK*coup + dto          (|d| <= 0.3)
//   sd  = d(1 - d^2/6)
//   cm1 = cd - 1 = d^2(-1/2 + d^2/24)   (|cm1| <= 0.045)
//   os  = fs + (fs*cm1 + fc*sd) ;  oc = fc + (fc*cm1 - fs*sd)
__device__ __forceinline__ void rot16(u32 fs, u32 fc, u32 sn, u32 cn, u32 dtoh,
                                      const SCH& H, u32& os, u32& oc) {
    u32 coup = hfma2(fc, sn, hneg2(hmul2(fs, cn)));
    u32 d = hfma2(H.DTKh, coup, dtoh);
    u32 d2 = hmul2(d, d);
    u32 sd = hmul2(d, hfma2(d2, H.C3h, H.ONEh));
    u32 cm1 = hmul2(d2, hfma2(d2, H.C24h, H.mHh));
    u32 ms = hneg2(fs);
    os = hadd2(fs, hfma2(fs, cm1, hmul2(fc, sd)));
    oc = hadd2(fc, hfma2(fc, cm1, hmul2(ms, sd)));
}

// Final-step rotation (fp32 output): fp16 coupling, fp32 series.
__device__ __forceinline__ void rot_core(u32 fsh, u32 fch, u64 fs, u64 fc,
                                         u32 snh, u32 cnh,
                                         u64 dto, const SC& C,
                                         u64& os, u64& oc) {
    u32 coup_h = hfma2(fch, snh, hneg2(hmul2(fsh, cnh)));
    u64 d = fma2(C.DTK2, h2f(coup_h), dto);
    u64 d2 = mul2(d, d);
    u64 sd = mul2(d, fma2(d2, C.C3, C.ONE2));
    u64 cd = fma2(d2, fma2(d2, C.C4, C.C2), C.ONE2);
    u64 m = neg2(fs);
    os = fma2(fs, cd, mul2(fc, sd));
    oc = fma2(fc, cd, mul2(m, sd));
}

// 64-block partial OR of (omega != 0). Pure function of input -> deterministic.
__global__ void __launch_bounds__(256) flag_kernel(const float* __restrict__ om) {
    const float4* om4 = (const float4*)om;
    int acc = 0;
    for (int i = blockIdx.x * 256 + threadIdx.x; i < HW / 4; i += 64 * 256) {
        float4 v = om4[i];
        acc |= (v.x != 0.f) | (v.y != 0.f) | (v.z != 0.f) | (v.w != 0.f);
    }
    int any = __syncthreads_or(acc);
    if (threadIdx.x == 0) g_parts[blockIdx.x] = any;
}

template <int PHASE>  // 0: x_img -> g_state ; 1: g_state -> out
__global__ void __launch_bounds__(NTHREADS, 2)
fused5_kernel(const float* __restrict__ x_img,
              const float* __restrict__ omega,
              const float* __restrict__ Kp,
              float* __restrict__ out) {
    extern __shared__ uint4 sm4[];
    uint4* bufA = sm4;
    uint4* bufB = sm4 + SMP;

    const int tid = threadIdx.x;
    const int t = tid % TCOLS;         // owns pixel cols 2t, 2t+1
    const int strip = tid / TCOLS;
    const int r0p = 1 + strip * PACKS_PER;
    const int b = blockIdx.y;
    const int y0 = blockIdx.x * TY;
    const int xe = 2 * t;
    const int ic = t + 1;              // own cell within row
    const float2* __restrict__ om2 = (const float2*)omega;

    const float DTK = DTc * Kp[0];
    SC C;
    C.DTK2 = pk2(DTK, DTK);
    C.ONE2 = pk2(1.0f, 1.0f);
    C.C3 = pk2(-1.0f / 6.0f, -1.0f / 6.0f);
    C.C2 = pk2(-0.5f, -0.5f);
    C.C4 = pk2(4.1666668e-2f, 4.1666668e-2f);
    SCH H;
    H.DTKh = fpair2h(DTK, DTK);
    H.ONEh = 0x3C003C00u;
    H.C3h = fpair2h(-1.0f / 6.0f, -1.0f / 6.0f);
    H.mHh = fpair2h(-0.5f, -0.5f);
    H.C24h = fpair2h(1.0f / 24.0f, 1.0f / 24.0f);

    // Zero pad ring of both buffers (h2 zero bits = 0.0).
    const uint4 Z = make_uint4(0u, 0u, 0u, 0u);
    for (int i = tid; i < CW; i += NTHREADS) {
        bufA[i] = Z; bufA[(RPP - 1) * CW + i] = Z;
        bufB[i] = Z; bufB[(RPP - 1) * CW + i] = Z;
    }
    for (int r = 1 + tid; r < RPP - 1; r += NTHREADS) {
        bufA[r * CW] = Z; bufA[r * CW + CW - 1] = Z;
        bufB[r * CW] = Z; bufB[r * CW + CW - 1] = Z;
    }

    // Init state into bufA; out-of-image rows = exact 0.
#pragma unroll
    for (int j = 0; j < PACKS_PER; j++) {
        const int rp = r0p + j;
        const int gy0 = y0 - HALO + 2 * (rp - 1);
        const int gy1 = gy0 + 1;
        const bool in0 = (gy0 >= 0) && (gy0 < HH);
        const bool in1 = (gy1 >= 0) && (gy1 < HH);
        if (PHASE == 0) {
            float sE0 = 0.f, cE0 = 0.f, sO0 = 0.f, cO0 = 0.f;
            float sE1 = 0.f, cE1 = 0.f, sO1 = 0.f, cO1 = 0.f;
            if (in0) {
                float2 v = *(const float2*)&x_img[b * HW + gy0 * WW + xe];
                __sincosf(fmaf(2.0f * PIf, v.x, -PIf), &sE0, &cE0);
                __sincosf(fmaf(2.0f * PIf, v.y, -PIf), &sO0, &cO0);
            }
            if (in1) {
                float2 v = *(const float2*)&x_img[b * HW + gy1 * WW + xe];
                __sincosf(fmaf(2.0f * PIf, v.x, -PIf), &sE1, &cE1);
                __sincosf(fmaf(2.0f * PIf, v.y, -PIf), &sO1, &cO1);
            }
            bufA[rp * CW + ic] = make_uint4(fpair2h(sE0, sE1), fpair2h(cE0, cE1),
                                            fpair2h(sO0, sO1), fpair2h(cO0, cO1));
        } else {
            // fp16 in, fp16 cells out: pure PRMT repack, zero conversions.
            uint2 v0 = in0 ? g_state[(long)b * HW2 + gy0 * TCOLS + t] : make_uint2(0u, 0u);
            uint2 v1 = in1 ? g_state[(long)b * HW2 + gy1 * TCOLS + t] : make_uint2(0u, 0u);
            bufA[rp * CW + ic] = make_uint4(los16(v0.x, v1.x), los16(v0.y, v1.y),
                                            his16(v0.x, v1.x), his16(v0.y, v1.y));
        }
    }

    // Fold the omega flag (doubles as the post-init barrier).
    int pf = (tid < 64) ? g_parts[tid] : 0;
    const int flg = __syncthreads_or(pf);

    const int gybase = y0 - HALO + 2 * (r0p - 1);
    const uint4* p = bufA;
    uint4* q = bufB;

    // Steps 1..HALO-1: smem -> smem, fully fp16 (zero conversions).
#pragma unroll 1
    for (int st = 0; st < HALO - 1; st++) {
        int idx = r0p * CW + ic;
        uint4 t4 = p[idx - CW];
        uint4 c4 = p[idx];
        u32 uEs = hadd2(t4.x, c4.x), uEc = hadd2(t4.y, c4.y);
        u32 uOs = hadd2(t4.z, c4.z), uOc = hadd2(t4.w, c4.w);
        // Prologue loads for iter 0.
        uint4 n4 = p[idx + CW];
        uint2 lf = lds8(p, idx - 1, 8);   // left cell O-half: (sO, cO) of col 2t-1
        uint2 rg = lds8(p, idx + 1, 0);   // right cell E-half: (sE, cE) of col 2t+2
#pragma unroll
        for (int j = 0; j < PACKS_PER; j++) {
            // Prefetch next iteration's loads ahead of this iteration's compute.
            uint4 n42; uint2 lf2, rg2;
            if (j < PACKS_PER - 1) {
                n42 = p[idx + 2 * CW];
                lf2 = lds8(p, idx + CW - 1, 8);
                rg2 = lds8(p, idx + CW + 1, 0);
            }

            u32 vEs = hadd2(c4.x, n4.x), vEc = hadd2(c4.y, n4.y);
            u32 vOs = hadd2(c4.z, n4.z), vOc = hadd2(c4.w, n4.w);
            u32 snE = hadd2(funnel16(uEs, vEs), hadd2(lf.x, c4.z));
            u32 cnE = hadd2(funnel16(uEc, vEc), hadd2(lf.y, c4.w));
            u32 snO = hadd2(funnel16(uOs, vOs), hadd2(c4.x, rg.x));
            u32 cnO = hadd2(funnel16(uOc, vOc), hadd2(c4.y, rg.y));

            u32 dtoEh = 0, dtoOh = 0;
            if (flg) {   // uniform branch; omega==0 fast path skips
                const int gy0 = gybase + 2 * j, gy1 = gy0 + 1;
                float2 o0 = (gy0 >= 0 && gy0 < HH) ? om2[gy0 * TCOLS + t] : make_float2(0.f, 0.f);
                float2 o1 = (gy1 >= 0 && gy1 < HH) ? om2[gy1 * TCOLS + t] : make_float2(0.f, 0.f);
                dtoEh = fpair2h(DTc * o0.x, DTc * o1.x);
                dtoOh = fpair2h(DTc * o0.y, DTc * o1.y);
            }

            u32 osE, ocE, osO, ocO;
            rot16(c4.x, c4.y, snE, cnE, dtoEh, H, osE, ocE);
            rot16(c4.z, c4.w, snO, cnO, dtoOh, H, osO, ocO);
            q[idx] = make_uint4(osE, ocE, osO, ocO);

            uEs = vEs; uEc = vEc; uOs = vOs; uOc = vOc;
            c4 = n4;
            n4 = n42; lf = lf2; rg = rg2;
            idx += CW;
        }
        __syncthreads();
        const uint4* tp = q;
        q = (uint4*)p;
        p = tp;
    }

    // Final step: compute fp32, write interior rows straight to global.
    {
        int idx = r0p * CW + ic;
        uint4 t4 = p[idx - CW];
        uint4 c4 = p[idx];
        u32 uEs = hadd2(t4.x, c4.x), uEc = hadd2(t4.y, c4.y);
        u32 uOs = hadd2(t4.z, c4.z), uOc = hadd2(t4.w, c4.w);
        u64 fEs = h2f(c4.x), fEc = h2f(c4.y);
        u64 fOs = h2f(c4.z), fOc = h2f(c4.w);
        uint4 n4 = p[idx + CW];
        uint2 lf = lds8(p, idx - 1, 8);
        uint2 rg = lds8(p, idx + 1, 0);
#pragma unroll
        for (int j = 0; j < PACKS_PER; j++) {
            uint4 n42; uint2 lf2, rg2;
            if (j < PACKS_PER - 1) {
                n42 = p[idx + 2 * CW];
                lf2 = lds8(p, idx + CW - 1, 8);
                rg2 = lds8(p, idx + CW + 1, 0);
            }

            u32 vEs = hadd2(c4.x, n4.x), vEc = hadd2(c4.y, n4.y);
            u32 vOs = hadd2(c4.z, n4.z), vOc = hadd2(c4.w, n4.w);
            u32 snE = hadd2(funnel16(uEs, vEs), hadd2(lf.x, c4.z));
            u32 cnE = hadd2(funnel16(uEc, vEc), hadd2(lf.y, c4.w));
            u32 snO = hadd2(funnel16(uOs, vOs), hadd2(c4.x, rg.x));
            u32 cnO = hadd2(funnel16(uOc, vOc), hadd2(c4.y, rg.y));

            u64 dtoE = 0, dtoO = 0;
            if (flg) {
                const int gy0 = gybase + 2 * j, gy1 = gy0 + 1;
                float2 o0 = (gy0 >= 0 && gy0 < HH) ? om2[gy0 * TCOLS + t] : make_float2(0.f, 0.f);
                float2 o1 = (gy1 >= 0 && gy1 < HH) ? om2[gy1 * TCOLS + t] : make_float2(0.f, 0.f);
                dtoE = pk2(DTc * o0.x, DTc * o1.x);
                dtoO = pk2(DTc * o0.y, DTc * o1.y);
            }

            u64 osE, ocE, osO, ocO;
            rot_core(c4.x, c4.y, fEs, fEc, snE, cnE, dtoE, C, osE, ocE);
            rot_core(c4.z, c4.w, fOs, fOc, snO, cnO, dtoO, C, osO, ocO);

            float se0, se1, ce0, ce1, so0, so1, co0, co1;
            unpk2(osE, se0, se1); unpk2(ocE, ce0, ce1);
            unpk2(osO, so0, so1); unpk2(ocO, co0, co1);
            const int rt0 = 2 * (r0p + j - 1);
#pragma unroll
            for (int par = 0; par < 2; par++) {
                const int rt = rt0 + par;
                if (rt >= HALO && rt < HALO + TY) {
                    const int gy = y0 + (rt - HALO);
                    if (gy < HH) {
                        float ws0 = par ? se1 : se0;   // s col 2t
                        float ws1 = par ? so1 : so0;   // s col 2t+1
                        float wc0 = par ? ce1 : ce0;   // c col 2t
                        float wc1 = par ? co1 : co0;   // c col 2t+1
                        if (PHASE == 0) {
                            g_state[(long)b * HW2 + gy * TCOLS + t] =
                                make_uint2(fpair2h(ws0, ws1), fpair2h(wc0, wc1));
                        } else {
                            const int pix = gy * WW + xe;
                            *(float2*)&out[(long)b * (2 * HW) + pix] = make_float2(wc0, wc1);
                            *(float2*)&out[(long)b * (2 * HW) + HW + pix] = make_float2(ws0, ws1);
                        }
                    }
                }
            }

            uEs = vEs; uEc = vEc; uOs = vOs; uOc = vOc;
            c4 = n4;
            fEs = h2f(n4.x); fEc = h2f(n4.y);
            fOs = h2f(n4.z); fOc = h2f(n4.w);
            n4 = n42; lf = lf2; rg = rg2;
            idx += CW;
        }
    }
}

extern "C" void kernel_launch(void* const* d_in, const int* in_sizes, int n_in,
                              void* d_out, int out_size) {
    const float* x_img = (const float*)d_in[0];  // (B,1,H,W)
    const float* omega = (const float*)d_in[1];  // (1,1,H,W)
    const float* Kp    = (const float*)d_in[2];  // scalar
    float* out = (float*)d_out;

    static bool configured = false;
    if (!configured) {
        cudaFuncSetAttribute(fused5_kernel<0>,
                             cudaFuncAttributeMaxDynamicSharedMemorySize, SMEM_BYTES);
        cudaFuncSetAttribute(fused5_kernel<1>,
                             cudaFuncAttributeMaxDynamicSharedMemorySize, SMEM_BYTES);
        configured = true;
    }

    flag_kernel<<<64, 256>>>(omega);

    dim3 grid(TILES, BB);
    dim3 block(NTHREADS);
    fused5_kernel<0><<<grid, block, SMEM_BYTES>>>(x_img, omega, Kp, out);
    fused5_kernel<1><<<grid, block, SMEM_BYTES>>>(x_img, omega, Kp, out);
}

// round 16
// speedup vs baseline: 1.2485x; 1.0490x over previous
#include <cuda_runtime.h>

#define HH 224
#define WW 224
#define HW (HH * WW)
#define HW2 (HW / 2)
#define BB 256
#define NTOT (BB * HW)
#define DTc 0.15f
#define PIf 3.14159265358979f

#define TY 46                  // interior rows per tile
#define HALO 5                 // 5 fused steps per kernel
#define RR (TY + 2 * HALO)     // 56 data rows
#define RPAIRS (RR / 2)        // 28 vertical row-pair packs
#define RPP (RPAIRS + 2)       // +2 zero-pad pack rows -> 30
#define TCOLS 112              // thread-columns (each owns 2 pixel cols)
#define CW 114                 // cells per pack row incl 2 pads
#define TILES 5                // 5*46 = 230 >= 224
#define STRIPS 4
#define NTHREADS (TCOLS * STRIPS)    // 448; 2 CTAs/SM
#define PACKS_PER (RPAIRS / STRIPS)  // 7
#define SMP (RPP * CW)               // uint4 cells per buffer = 3420
#define SMEM_BYTES (2 * SMP * 16)    // 109440 B -> 2 CTAs/SM

typedef unsigned long long u64;
typedef unsigned int u32;

// Intermediate state between phases, fp16: per (batch, row, colpair) cell
// {s_h2 = (s_col2t, s_col2t+1), c_h2 = (c_col2t, c_col2t+1)}.
__device__ uint2 g_state[(long)BB * HW2];
__device__ int g_parts[64];     // partial omega-nonzero flags

// ---- packed f32x2 helpers ----
__device__ __forceinline__ u64 pk2(float lo, float hi) {
    u64 r; asm("mov.b64 %0, {%1, %2};" : "=l"(r) : "f"(lo), "f"(hi)); return r;
}
__device__ __forceinline__ void unpk2(u64 v, float& lo, float& hi) {
    asm("mov.b64 {%0, %1}, %2;" : "=f"(lo), "=f"(hi) : "l"(v));
}
__device__ __forceinline__ u64 mul2(u64 a, u64 b) {
    u64 d; asm("mul.rn.f32x2 %0, %1, %2;" : "=l"(d) : "l"(a), "l"(b)); return d;
}
__device__ __forceinline__ u64 fma2(u64 a, u64 b, u64 c) {
    u64 d; asm("fma.rn.f32x2 %0, %1, %2, %3;" : "=l"(d) : "l"(a), "l"(b), "l"(c)); return d;
}
__device__ __forceinline__ u64 neg2(u64 a) { return a ^ 0x8000000080000000ULL; }

// ---- fp16x2 helpers ----
__device__ __forceinline__ u32 hadd2(u32 a, u32 b) {
    u32 d; asm("add.rn.f16x2 %0, %1, %2;" : "=r"(d) : "r"(a), "r"(b)); return d;
}
__device__ __forceinline__ u32 hmul2(u32 a, u32 b) {
    u32 d; asm("mul.rn.f16x2 %0, %1, %2;" : "=r"(d) : "r"(a), "r"(b)); return d;
}
__device__ __forceinline__ u32 hfma2(u32 a, u32 b, u32 c) {
    u32 d; asm("fma.rn.f16x2 %0, %1, %2, %3;" : "=r"(d) : "r"(a), "r"(b), "r"(c)); return d;
}
__device__ __forceinline__ u32 hneg2(u32 a) { return a ^ 0x80008000u; }
// (a.hi16, b.lo16)
__device__ __forceinline__ u32 funnel16(u32 a, u32 b) {
    u32 d; asm("prmt.b32 %0, %1, %2, 0x5432;" : "=r"(d) : "r"(a), "r"(b)); return d;
}
// (a.lo16, b.lo16)
__device__ __forceinline__ u32 los16(u32 a, u32 b) {
    u32 d; asm("prmt.b32 %0, %1, %2, 0x5410;" : "=r"(d) : "r"(a), "r"(b)); return d;
}
// (a.hi16, b.hi16)
__device__ __forceinline__ u32 his16(u32 a, u32 b) {
    u32 d; asm("prmt.b32 %0, %1, %2, 0x7632;" : "=r"(d) : "r"(a), "r"(b)); return d;
}
__device__ __forceinline__ u64 h2f(u32 h) {
    float lo, hi;
    asm("{\n\t.reg .b16 l, h;\n\tmov.b32 {l, h}, %2;\n\t"
        "cvt.f32.f16 %0, l;\n\tcvt.f32.f16 %1, h;\n\t}"
        : "=f"(lo), "=f"(hi) : "r"(h));
    return pk2(lo, hi);
}
__device__ __forceinline__ u32 fpair2h(float lo, float hi) {
    u32 d; asm("cvt.rn.f16x2.f32 %0, %1, %2;" : "=r"(d) : "f"(hi), "f"(lo)); return d;
}
__device__ __forceinline__ u32 f2h(u64 v) {
    float lo, hi; unpk2(v, lo, hi); return fpair2h(lo, hi);
}

// 8-byte half-cell shared load: half=0 -> (x,y), half=8 -> (z,w).
__device__ __forceinline__ uint2 lds8(const uint4* buf, int cellIdx, int halfBytes) {
    return *(const uint2*)((const char*)(buf + cellIdx) + halfBytes);
}

struct SC { u64 DTK2, ONE2, C3, C2, C4; };
struct SCH { u32 DTKh, ONEh, C3h, mHh; };  // fp16x2 constants

// Middle-step rotation, 100% fp16 (delta form):
//   d   = DTK*coup (+ dto)        (|d| <= 0.3)
//   sd  = d(1 - d^2/6)
//   cm1 = cd - 1 ~= -d^2/2        (d^4/24 term below fp16 noise, dropped)
//   os  = fs + (fs*cm1 + fc*sd) ;  oc = fc + (fc*cm1 - fs*sd)
template <bool OMG>
__device__ __forceinline__ void rot16(u32 fs, u32 fc, u32 sn, u32 cn, u32 dtoh,
                                      const SCH& H, u32& os, u32& oc) {
    u32 coup = hfma2(fc, sn, hneg2(hmul2(fs, cn)));
    u32 d = OMG ? hfma2(H.DTKh, coup, dtoh) : hmul2(H.DTKh, coup);
    u32 d2 = hmul2(d, d);
    u32 sd = hmul2(d, hfma2(d2, H.C3h, H.ONEh));
    u32 cm1 = hmul2(d2, H.mHh);
    u32 ms = hneg2(fs);
    os = hadd2(fs, hfma2(fs, cm1, hmul2(fc, sd)));
    oc = hadd2(fc, hfma2(fc, cm1, hmul2(ms, sd)));
}

// Final-step rotation (fp32 output): fp16 coupling, full fp32 series.
template <bool OMG>
__device__ __forceinline__ void rot_core(u32 fsh, u32 fch, u64 fs, u64 fc,
                                         u32 snh, u32 cnh,
                                         u64 dto, const SC& C,
                                         u64& os, u64& oc) {
    u32 coup_h = hfma2(fch, snh, hneg2(hmul2(fsh, cnh)));
    u64 d = OMG ? fma2(C.DTK2, h2f(coup_h), dto) : mul2(C.DTK2, h2f(coup_h));
    u64 d2 = mul2(d, d);
    u64 sd = mul2(d, fma2(d2, C.C3, C.ONE2));
    u64 cd = fma2(d2, fma2(d2, C.C4, C.C2), C.ONE2);
    u64 m = neg2(fs);
    os = fma2(fs, cd, mul2(fc, sd));
    oc = fma2(fc, cd, mul2(m, sd));
}

// 64-block partial OR of (omega != 0). Pure function of input -> deterministic.
__global__ void __launch_bounds__(256) flag_kernel(const float* __restrict__ om) {
    const float4* om4 = (const float4*)om;
    int acc = 0;
    for (int i = blockIdx.x * 256 + threadIdx.x; i < HW / 4; i += 64 * 256) {
        float4 v = om4[i];
        acc |= (v.x != 0.f) | (v.y != 0.f) | (v.z != 0.f) | (v.w != 0.f);
    }
    int any = __syncthreads_or(acc);
    if (threadIdx.x == 0) g_parts[blockIdx.x] = any;
}

// Middle steps + final step, with the omega path resolved at compile time.
template <int PHASE, bool OMG>
__device__ __forceinline__ void run_steps(
    const uint4* p, uint4* q, int r0p, int ic, int t,
    int gybase, int y0, int b, int xe,
    const SC& C, const SCH& H,
    const float2* __restrict__ om2, float* __restrict__ out)
{
    // Steps 1..HALO-1: smem -> smem, fully fp16.
#pragma unroll 1
    for (int st = 0; st < HALO - 1; st++) {
        int idx = r0p * CW + ic;
        uint4 t4 = p[idx - CW];
        uint4 c4 = p[idx];
        u32 uEs = hadd2(t4.x, c4.x), uEc = hadd2(t4.y, c4.y);
        u32 uOs = hadd2(t4.z, c4.z), uOc = hadd2(t4.w, c4.w);
        // Prologue loads for iter 0.
        uint4 n4 = p[idx + CW];
        uint2 lf = lds8(p, idx - 1, 8);   // left cell O-half
        uint2 rg = lds8(p, idx + 1, 0);   // right cell E-half
#pragma unroll
        for (int j = 0; j < PACKS_PER; j++) {
            uint4 n42; uint2 lf2, rg2;
            if (j < PACKS_PER - 1) {
                n42 = p[idx + 2 * CW];
                lf2 = lds8(p, idx + CW - 1, 8);
                rg2 = lds8(p, idx + CW + 1, 0);
            }

            u32 vEs = hadd2(c4.x, n4.x), vEc = hadd2(c4.y, n4.y);
            u32 vOs = hadd2(c4.z, n4.z), vOc = hadd2(c4.w, n4.w);
            u32 snE = hadd2(funnel16(uEs, vEs), hadd2(lf.x, c4.z));
            u32 cnE = hadd2(funnel16(uEc, vEc), hadd2(lf.y, c4.w));
            u32 snO = hadd2(funnel16(uOs, vOs), hadd2(c4.x, rg.x));
            u32 cnO = hadd2(funnel16(uOc, vOc), hadd2(c4.y, rg.y));

            u32 dtoEh = 0, dtoOh = 0;
            if (OMG) {
                const int gy0 = gybase + 2 * j, gy1 = gy0 + 1;
                float2 o0 = (gy0 >= 0 && gy0 < HH) ? om2[gy0 * TCOLS + t] : make_float2(0.f, 0.f);
                float2 o1 = (gy1 >= 0 && gy1 < HH) ? om2[gy1 * TCOLS + t] : make_float2(0.f, 0.f);
                dtoEh = fpair2h(DTc * o0.x, DTc * o1.x);
                dtoOh = fpair2h(DTc * o0.y, DTc * o1.y);
            }

            u32 osE, ocE, osO, ocO;
            rot16<OMG>(c4.x, c4.y, snE, cnE, dtoEh, H, osE, ocE);
            rot16<OMG>(c4.z, c4.w, snO, cnO, dtoOh, H, osO, ocO);
            q[idx] = make_uint4(osE, ocE, osO, ocO);

            uEs = vEs; uEc = vEc; uOs = vOs; uOc = vOc;
            c4 = n4;
            n4 = n42; lf = lf2; rg = rg2;
            idx += CW;
        }
        __syncthreads();
        const uint4* tp = q;
        q = (uint4*)p;
        p = tp;
    }

    // Final step: compute fp32, write interior rows straight to global.
    {
        int idx = r0p * CW + ic;
        uint4 t4 = p[idx - CW];
        uint4 c4 = p[idx];
        u32 uEs = hadd2(t4.x, c4.x), uEc = hadd2(t4.y, c4.y);
        u32 uOs = hadd2(t4.z, c4.z), uOc = hadd2(t4.w, c4.w);
        u64 fEs = h2f(c4.x), fEc = h2f(c4.y);
        u64 fOs = h2f(c4.z), fOc = h2f(c4.w);
        uint4 n4 = p[idx + CW];
        uint2 lf = lds8(p, idx - 1, 8);
        uint2 rg = lds8(p, idx + 1, 0);
#pragma unroll
        for (int j = 0; j < PACKS_PER; j++) {
            uint4 n42; uint2 lf2, rg2;
            if (j < PACKS_PER - 1) {
                n42 = p[idx + 2 * CW];
                lf2 = lds8(p, idx + CW - 1, 8);
                rg2 = lds8(p, idx + CW + 1, 0);
            }

            u32 vEs = hadd2(c4.x, n4.x), vEc = hadd2(c4.y, n4.y);
            u32 vOs = hadd2(c4.z, n4.z), vOc = hadd2(c4.w, n4.w);
            u32 snE = hadd2(funnel16(uEs, vEs), hadd2(lf.x, c4.z));
            u32 cnE = hadd2(funnel16(uEc, vEc), hadd2(lf.y, c4.w));
            u32 snO = hadd2(funnel16(uOs, vOs), hadd2(c4.x, rg.x));
            u32 cnO = hadd2(funnel16(uOc, vOc), hadd2(c4.y, rg.y));

            u64 dtoE = 0, dtoO = 0;
            if (OMG) {
                const int gy0 = gybase + 2 * j, gy1 = gy0 + 1;
                float2 o0 = (gy0 >= 0 && gy0 < HH) ? om2[gy0 * TCOLS + t] : make_float2(0.f, 0.f);
                float2 o1 = (gy1 >= 0 && gy1 < HH) ? om2[gy1 * TCOLS + t] : make_float2(0.f, 0.f);
                dtoE = pk2(DTc * o0.x, DTc * o1.x);
                dtoO = pk2(DTc * o0.y, DTc * o1.y);
            }

            u64 osE, ocE, osO, ocO;
            rot_core<OMG>(c4.x, c4.y, fEs, fEc, snE, cnE, dtoE, C, osE, ocE);
            rot_core<OMG>(c4.z, c4.w, fOs, fOc, snO, cnO, dtoO, C, osO, ocO);

            float se0, se1, ce0, ce1, so0, so1, co0, co1;
            unpk2(osE, se0, se1); unpk2(ocE, ce0, ce1);
            unpk2(osO, so0, so1); unpk2(ocO, co0, co1);
            const int rt0 = 2 * (r0p + j - 1);
#pragma unroll
            for (int par = 0; par < 2; par++) {
                const int rt = rt0 + par;
                if (rt >= HALO && rt < HALO + TY) {
                    const int gy = y0 + (rt - HALO);
                    if (gy < HH) {
                        float ws0 = par ? se1 : se0;   // s col 2t
                        float ws1 = par ? so1 : so0;   // s col 2t+1
                        float wc0 = par ? ce1 : ce0;   // c col 2t
                        float wc1 = par ? co1 : co0;   // c col 2t+1
                        if (PHASE == 0) {
                            g_state[(long)b * HW2 + gy * TCOLS + t] =
                                make_uint2(fpair2h(ws0, ws1), fpair2h(wc0, wc1));
                        } else {
                            const int pix = gy * WW + xe;
                            *(float2*)&out[(long)b * (2 * HW) + pix] = make_float2(wc0, wc1);
                            *(float2*)&out[(long)b * (2 * HW) + HW + pix] = make_float2(ws0, ws1);
                        }
                    }
                }
            }

            uEs = vEs; uEc = vEc; uOs = vOs; uOc = vOc;
            c4 = n4;
            fEs = h2f(n4.x); fEc = h2f(n4.y);
            fOs = h2f(n4.z); fOc = h2f(n4.w);
            n4 = n42; lf = lf2; rg = rg2;
            idx += CW;
        }
    }
}

template <int PHASE>  // 0: x_img -> g_state ; 1: g_state -> out
__global__ void __launch_bounds__(NTHREADS, 2)
fused5_kernel(const float* __restrict__ x_img,
              const float* __restrict__ omega,
              const float* __restrict__ Kp,
              float* __restrict__ out) {
    extern __shared__ uint4 sm4[];
    uint4* bufA = sm4;
    uint4* bufB = sm4 + SMP;

    const int tid = threadIdx.x;
    const int t = tid % TCOLS;         // owns pixel cols 2t, 2t+1
    const int strip = tid / TCOLS;
    const int r0p = 1 + strip * PACKS_PER;
    const int b = blockIdx.y;
    const int y0 = blockIdx.x * TY;
    const int xe = 2 * t;
    const int ic = t + 1;              // own cell within row
    const float2* __restrict__ om2 = (const float2*)omega;

    const float DTK = DTc * Kp[0];
    SC C;
    C.DTK2 = pk2(DTK, DTK);
    C.ONE2 = pk2(1.0f, 1.0f);
    C.C3 = pk2(-1.0f / 6.0f, -1.0f / 6.0f);
    C.C2 = pk2(-0.5f, -0.5f);
    C.C4 = pk2(4.1666668e-2f, 4.1666668e-2f);
    SCH H;
    H.DTKh = fpair2h(DTK, DTK);
    H.ONEh = 0x3C003C00u;
    H.C3h = fpair2h(-1.0f / 6.0f, -1.0f / 6.0f);
    H.mHh = fpair2h(-0.5f, -0.5f);

    // Zero pad ring of both buffers (h2 zero bits = 0.0).
    const uint4 Z = make_uint4(0u, 0u, 0u, 0u);
    for (int i = tid; i < CW; i += NTHREADS) {
        bufA[i] = Z; bufA[(RPP - 1) * CW + i] = Z;
        bufB[i] = Z; bufB[(RPP - 1) * CW + i] = Z;
    }
    for (int r = 1 + tid; r < RPP - 1; r += NTHREADS) {
        bufA[r * CW] = Z; bufA[r * CW + CW - 1] = Z;
        bufB[r * CW] = Z; bufB[r * CW + CW - 1] = Z;
    }

    // Init state into bufA; out-of-image rows = exact 0.
#pragma unroll
    for (int j = 0; j < PACKS_PER; j++) {
        const int rp = r0p + j;
        const int gy0 = y0 - HALO + 2 * (rp - 1);
        const int gy1 = gy0 + 1;
        const bool in0 = (gy0 >= 0) && (gy0 < HH);
        const bool in1 = (gy1 >= 0) && (gy1 < HH);
        if (PHASE == 0) {
            float sE0 = 0.f, cE0 = 0.f, sO0 = 0.f, cO0 = 0.f;
            float sE1 = 0.f, cE1 = 0.f, sO1 = 0.f, cO1 = 0.f;
            if (in0) {
                float2 v = *(const float2*)&x_img[b * HW + gy0 * WW + xe];
                __sincosf(fmaf(2.0f * PIf, v.x, -PIf), &sE0, &cE0);
                __sincosf(fmaf(2.0f * PIf, v.y, -PIf), &sO0, &cO0);
            }
            if (in1) {
                float2 v = *(const float2*)&x_img[b * HW + gy1 * WW + xe];
                __sincosf(fmaf(2.0f * PIf, v.x, -PIf), &sE1, &cE1);
                __sincosf(fmaf(2.0f * PIf, v.y, -PIf), &sO1, &cO1);
            }
            bufA[rp * CW + ic] = make_uint4(fpair2h(sE0, sE1), fpair2h(cE0, cE1),
                                            fpair2h(sO0, sO1), fpair2h(cO0, cO1));
        } else {
            // fp16 in, fp16 cells out: pure PRMT repack, zero conversions.
            uint2 v0 = in0 ? g_state[(long)b * HW2 + gy0 * TCOLS + t] : make_uint2(0u, 0u);
            uint2 v1 = in1 ? g_state[(long)b * HW2 + gy1 * TCOLS + t] : make_uint2(0u, 0u);
            bufA[rp * CW + ic] = make_uint4(los16(v0.x, v1.x), los16(v0.y, v1.y),
                                            his16(v0.x, v1.x), his16(v0.y, v1.y));
        }
    }

    // Fold the omega flag (doubles as the post-init barrier).
    int pf = (tid < 64) ? g_parts[tid] : 0;
    const int flg = __syncthreads_or(pf);

    const int gybase = y0 - HALO + 2 * (r0p - 1);

    // Uniform branch: omega machinery compiled out of the hot path.
    if (flg)
        run_steps<PHASE, true>(bufA, bufB, r0p, ic, t, gybase, y0, b, xe, C, H, om2, out);
    else
        run_steps<PHASE, false>(bufA, bufB, r0p, ic, t, gybase, y0, b, xe, C, H, om2, out);
}

extern "C" void kernel_launch(void* const* d_in, const int* in_sizes, int n_in,
                              void* d_out, int out_size) {
    const float* x_img = (const float*)d_in[0];  // (B,1,H,W)
    const float* omega = (const float*)d_in[1];  // (1,1,H,W)
    const float* Kp    = (const float*)d_in[2];  // scalar
    float* out = (float*)d_out;

    static bool configured = false;
    if (!configured) {
        cudaFuncSetAttribute(fused5_kernel<0>,
                             cudaFuncAttributeMaxDynamicSharedMemorySize, SMEM_BYTES);
        cudaFuncSetAttribute(fused5_kernel<1>,
                             cudaFuncAttributeMaxDynamicSharedMemorySize, SMEM_BYTES);
        configured = true;
    }

    flag_kernel<<<64, 256>>>(omega);

    dim3 grid(TILES, BB);
    dim3 block(NTHREADS);
    fused5_kernel<0><<<grid, block, SMEM_BYTES>>>(x_img, omega, Kp, out);
    fused5_kernel<1><<<grid, block, SMEM_BYTES>>>(x_img, omega, Kp, out);
}

// round 17
// speedup vs baseline: 1.3511x; 1.0822x over previous
#include <cuda_runtime.h>

#define HH 224
#define WW 224
#define HW (HH * WW)
#define HW2 (HW / 2)
#define BB 256
#define NTOT (BB * HW)
#define DTc 0.15f
#define PIf 3.14159265358979f

#define TY 46                  // interior rows per tile
#define HALO 5                 // 5 fused steps per kernel
#define RR (TY + 2 * HALO)     // 56 data rows
#define RPAIRS (RR / 2)        // 28 vertical row-pair packs
#define RPP (RPAIRS + 2)       // +2 zero-pad pack rows -> 30
#define TCOLS 112              // thread-columns (each owns 2 pixel cols)
#define CW 114                 // cells per pack row incl 2 pads
#define TILES 5                // 5*46 = 230 >= 224
#define STRIPS 4
#define NTHREADS (TCOLS * STRIPS)    // 448; 2 CTAs/SM
#define PACKS_PER (RPAIRS / STRIPS)  // 7
#define SMP (RPP * CW)               // uint4 cells per buffer = 3420
#define SMEM_BYTES (2 * SMP * 16)    // 109440 B -> 2 CTAs/SM

typedef unsigned long long u64;
typedef unsigned int u32;

// Intermediate state between phases, fp16: per (batch, row, colpair) cell
// {s_h2 = (s_col2t, s_col2t+1), c_h2 = (c_col2t, c_col2t+1)}.
__device__ uint2 g_state[(long)BB * HW2];
__device__ int g_parts[64];     // partial omega-nonzero flags

// ---- packed f32x2 helpers ----
__device__ __forceinline__ u64 pk2(float lo, float hi) {
    u64 r; asm("mov.b64 %0, {%1, %2};" : "=l"(r) : "f"(lo), "f"(hi)); return r;
}
__device__ __forceinline__ void unpk2(u64 v, float& lo, float& hi) {
    asm("mov.b64 {%0, %1}, %2;" : "=f"(lo), "=f"(hi) : "l"(v));
}
__device__ __forceinline__ u64 mul2(u64 a, u64 b) {
    u64 d; asm("mul.rn.f32x2 %0, %1, %2;" : "=l"(d) : "l"(a), "l"(b)); return d;
}
__device__ __forceinline__ u64 fma2(u64 a, u64 b, u64 c) {
    u64 d; asm("fma.rn.f32x2 %0, %1, %2, %3;" : "=l"(d) : "l"(a), "l"(b), "l"(c)); return d;
}
__device__ __forceinline__ u64 neg2(u64 a) { return a ^ 0x8000000080000000ULL; }

// ---- fp16x2 helpers ----
__device__ __forceinline__ u32 hadd2(u32 a, u32 b) {
    u32 d; asm("add.rn.f16x2 %0, %1, %2;" : "=r"(d) : "r"(a), "r"(b)); return d;
}
__device__ __forceinline__ u32 hmul2(u32 a, u32 b) {
    u32 d; asm("mul.rn.f16x2 %0, %1, %2;" : "=r"(d) : "r"(a), "r"(b)); return d;
}
__device__ __forceinline__ u32 hfma2(u32 a, u32 b, u32 c) {
    u32 d; asm("fma.rn.f16x2 %0, %1, %2, %3;" : "=r"(d) : "r"(a), "r"(b), "r"(c)); return d;
}
__device__ __forceinline__ u32 hneg2(u32 a) { return a ^ 0x80008000u; }
// (a.hi16, b.lo16)
__device__ __forceinline__ u32 funnel16(u32 a, u32 b) {
    u32 d; asm("prmt.b32 %0, %1, %2, 0x5432;" : "=r"(d) : "r"(a), "r"(b)); return d;
}
// (a.lo16, b.lo16)
__device__ __forceinline__ u32 los16(u32 a, u32 b) {
    u32 d; asm("prmt.b32 %0, %1, %2, 0x5410;" : "=r"(d) : "r"(a), "r"(b)); return d;
}
// (a.hi16, b.hi16)
__device__ __forceinline__ u32 his16(u32 a, u32 b) {
    u32 d; asm("prmt.b32 %0, %1, %2, 0x7632;" : "=r"(d) : "r"(a), "r"(b)); return d;
}
__device__ __forceinline__ u64 h2f(u32 h) {
    float lo, hi;
    asm("{\n\t.reg .b16 l, h;\n\tmov.b32 {l, h}, %2;\n\t"
        "cvt.f32.f16 %0, l;\n\tcvt.f32.f16 %1, h;\n\t}"
        : "=f"(lo), "=f"(hi) : "r"(h));
    return pk2(lo, hi);
}
__device__ __forceinline__ u32 fpair2h(float lo, float hi) {
    u32 d; asm("cvt.rn.f16x2.f32 %0, %1, %2;" : "=r"(d) : "f"(hi), "f"(lo)); return d;
}
__device__ __forceinline__ u32 f2h(u64 v) {
    float lo, hi; unpk2(v, lo, hi); return fpair2h(lo, hi);
}

// 8-byte half-cell shared load: half=0 -> (x,y), half=8 -> (z,w).
__device__ __forceinline__ uint2 lds8(const uint4* buf, int cellIdx, int halfBytes) {
    return *(const uint2*)((const char*)(buf + cellIdx) + halfBytes);
}

struct SC { u64 DTK2, ONE2, C3, C2, C4; };
struct SCH { u32 DTKh, ONEh, C3h, mHh; };  // fp16x2 constants

// Middle-step rotation, 100% fp16 (delta form, pure FMA chains):
//   d   = DTK*coup (+ dto)        (|d| <= 0.3)
//   sd  = d(1 - d^2/6)
//   cm1 = -d^2/2
//   os  = (fs + fc*sd) + fs*cm1   as  hfma2(fs, cm1, hfma2(fc, sd, fs))
//   oc  = (fc - fs*sd) + fc*cm1   as  hfma2(fc, cm1, hfma2(-fs, sd, fc))
template <bool OMG>
__device__ __forceinline__ void rot16(u32 fs, u32 fc, u32 sn, u32 cn, u32 dtoh,
                                      const SCH& H, u32& os, u32& oc) {
    u32 coup = hfma2(fc, sn, hneg2(hmul2(fs, cn)));
    u32 d = OMG ? hfma2(H.DTKh, coup, dtoh) : hmul2(H.DTKh, coup);
    u32 d2 = hmul2(d, d);
    u32 sd = hmul2(d, hfma2(d2, H.C3h, H.ONEh));
    u32 cm1 = hmul2(d2, H.mHh);
    os = hfma2(fs, cm1, hfma2(fc, sd, fs));
    oc = hfma2(fc, cm1, hfma2(hneg2(fs), sd, fc));
}

// Final-step rotation (fp32 output): fp16 coupling, full fp32 series.
template <bool OMG>
__device__ __forceinline__ void rot_core(u32 fsh, u32 fch, u64 fs, u64 fc,
                                         u32 snh, u32 cnh,
                                         u64 dto, const SC& C,
                                         u64& os, u64& oc) {
    u32 coup_h = hfma2(fch, snh, hneg2(hmul2(fsh, cnh)));
    u64 d = OMG ? fma2(C.DTK2, h2f(coup_h), dto) : mul2(C.DTK2, h2f(coup_h));
    u64 d2 = mul2(d, d);
    u64 sd = mul2(d, fma2(d2, C.C3, C.ONE2));
    u64 cd = fma2(d2, fma2(d2, C.C4, C.C2), C.ONE2);
    u64 m = neg2(fs);
    os = fma2(fs, cd, mul2(fc, sd));
    oc = fma2(fc, cd, mul2(m, sd));
}

// 64-block partial OR of (omega != 0). Pure function of input -> deterministic.
__global__ void __launch_bounds__(256) flag_kernel(const float* __restrict__ om) {
    const float4* om4 = (const float4*)om;
    int acc = 0;
    for (int i = blockIdx.x * 256 + threadIdx.x; i < HW / 4; i += 64 * 256) {
        float4 v = om4[i];
        acc |= (v.x != 0.f) | (v.y != 0.f) | (v.z != 0.f) | (v.w != 0.f);
    }
    int any = __syncthreads_or(acc);
    if (threadIdx.x == 0) g_parts[blockIdx.x] = any;
}

// Middle steps + final step, with the omega path resolved at compile time.
template <int PHASE, bool OMG>
__device__ __forceinline__ void run_steps(
    const uint4* p, uint4* q, int r0p, int ic, int t,
    int gybase, int y0, int b, int xe,
    const SC& C, const SCH& H,
    const float2* __restrict__ om2, float* __restrict__ out)
{
    // Steps 1..HALO-1: smem -> smem, fully fp16.
#pragma unroll 1
    for (int st = 0; st < HALO - 1; st++) {
        int idx = r0p * CW + ic;
        uint4 t4 = p[idx - CW];
        uint4 c4 = p[idx];
        u32 uEs = hadd2(t4.x, c4.x), uEc = hadd2(t4.y, c4.y);
        u32 uOs = hadd2(t4.z, c4.z), uOc = hadd2(t4.w, c4.w);
        // Prologue loads for iter 0.
        uint4 n4 = p[idx + CW];
        uint2 lf = lds8(p, idx - 1, 8);   // left cell O-half
        uint2 rg = lds8(p, idx + 1, 0);   // right cell E-half
#pragma unroll
        for (int j = 0; j < PACKS_PER; j++) {
            uint4 n42; uint2 lf2, rg2;
            if (j < PACKS_PER - 1) {
                n42 = p[idx + 2 * CW];
                lf2 = lds8(p, idx + CW - 1, 8);
                rg2 = lds8(p, idx + CW + 1, 0);
            }

            u32 vEs = hadd2(c4.x, n4.x), vEc = hadd2(c4.y, n4.y);
            u32 vOs = hadd2(c4.z, n4.z), vOc = hadd2(c4.w, n4.w);
            u32 snE = hadd2(funnel16(uEs, vEs), hadd2(lf.x, c4.z));
            u32 cnE = hadd2(funnel16(uEc, vEc), hadd2(lf.y, c4.w));
            u32 snO = hadd2(funnel16(uOs, vOs), hadd2(c4.x, rg.x));
            u32 cnO = hadd2(funnel16(uOc, vOc), hadd2(c4.y, rg.y));

            u32 dtoEh = 0, dtoOh = 0;
            if (OMG) {
                const int gy0 = gybase + 2 * j, gy1 = gy0 + 1;
                float2 o0 = (gy0 >= 0 && gy0 < HH) ? om2[gy0 * TCOLS + t] : make_float2(0.f, 0.f);
                float2 o1 = (gy1 >= 0 && gy1 < HH) ? om2[gy1 * TCOLS + t] : make_float2(0.f, 0.f);
                dtoEh = fpair2h(DTc * o0.x, DTc * o1.x);
                dtoOh = fpair2h(DTc * o0.y, DTc * o1.y);
            }

            u32 osE, ocE, osO, ocO;
            rot16<OMG>(c4.x, c4.y, snE, cnE, dtoEh, H, osE, ocE);
            rot16<OMG>(c4.z, c4.w, snO, cnO, dtoOh, H, osO, ocO);
            q[idx] = make_uint4(osE, ocE, osO, ocO);

            uEs = vEs; uEc = vEc; uOs = vOs; uOc = vOc;
            c4 = n4;
            n4 = n42; lf = lf2; rg = rg2;
            idx += CW;
        }
        __syncthreads();
        const uint4* tp = q;
        q = (uint4*)p;
        p = tp;
    }

    // Final step: compute fp32, write interior rows straight to global.
    {
        int idx = r0p * CW + ic;
        uint4 t4 = p[idx - CW];
        uint4 c4 = p[idx];
        u32 uEs = hadd2(t4.x, c4.x), uEc = hadd2(t4.y, c4.y);
        u32 uOs = hadd2(t4.z, c4.z), uOc = hadd2(t4.w, c4.w);
        u64 fEs = h2f(c4.x), fEc = h2f(c4.y);
        u64 fOs = h2f(c4.z), fOc = h2f(c4.w);
        uint4 n4 = p[idx + CW];
        uint2 lf = lds8(p, idx - 1, 8);
        uint2 rg = lds8(p, idx + 1, 0);
#pragma unroll
        for (int j = 0; j < PACKS_PER; j++) {
            uint4 n42; uint2 lf2, rg2;
            if (j < PACKS_PER - 1) {
                n42 = p[idx + 2 * CW];
                lf2 = lds8(p, idx + CW - 1, 8);
                rg2 = lds8(p, idx + CW + 1, 0);
            }

            u32 vEs = hadd2(c4.x, n4.x), vEc = hadd2(c4.y, n4.y);
            u32 vOs = hadd2(c4.z, n4.z), vOc = hadd2(c4.w, n4.w);
            u32 snE = hadd2(funnel16(uEs, vEs), hadd2(lf.x, c4.z));
            u32 cnE = hadd2(funnel16(uEc, vEc), hadd2(lf.y, c4.w));
            u32 snO = hadd2(funnel16(uOs, vOs), hadd2(c4.x, rg.x));
            u32 cnO = hadd2(funnel16(uOc, vOc), hadd2(c4.y, rg.y));

            u64 dtoE = 0, dtoO = 0;
            if (OMG) {
                const int gy0 = gybase + 2 * j, gy1 = gy0 + 1;
                float2 o0 = (gy0 >= 0 && gy0 < HH) ? om2[gy0 * TCOLS + t] : make_float2(0.f, 0.f);
                float2 o1 = (gy1 >= 0 && gy1 < HH) ? om2[gy1 * TCOLS + t] : make_float2(0.f, 0.f);
                dtoE = pk2(DTc * o0.x, DTc * o1.x);
                dtoO = pk2(DTc * o0.y, DTc * o1.y);
            }

            u64 osE, ocE, osO, ocO;
            rot_core<OMG>(c4.x, c4.y, fEs, fEc, snE, cnE, dtoE, C, osE, ocE);
            rot_core<OMG>(c4.z, c4.w, fOs, fOc, snO, cnO, dtoO, C, osO, ocO);

            float se0, se1, ce0, ce1, so0, so1, co0, co1;
            unpk2(osE, se0, se1); unpk2(ocE, ce0, ce1);
            unpk2(osO, so0, so1); unpk2(ocO, co0, co1);
            const int rt0 = 2 * (r0p + j - 1);
#pragma unroll
            for (int par = 0; par < 2; par++) {
                const int rt = rt0 + par;
                if (rt >= HALO && rt < HALO + TY) {
                    const int gy = y0 + (rt - HALO);
                    if (gy < HH) {
                        float ws0 = par ? se1 : se0;   // s col 2t
                        float ws1 = par ? so1 : so0;   // s col 2t+1
                        float wc0 = par ? ce1 : ce0;   // c col 2t
                        float wc1 = par ? co1 : co0;   // c col 2t+1
                        if (PHASE == 0) {
                            g_state[(long)b * HW2 + gy * TCOLS + t] =
                                make_uint2(fpair2h(ws0, ws1), fpair2h(wc0, wc1));
                        } else {
                            const int pix = gy * WW + xe;
                            *(float2*)&out[(long)b * (2 * HW) + pix] = make_float2(wc0, wc1);
                            *(float2*)&out[(long)b * (2 * HW) + HW + pix] = make_float2(ws0, ws1);
                        }
                    }
                }
            }

            uEs = vEs; uEc = vEc; uOs = vOs; uOc = vOc;
            c4 = n4;
            fEs = h2f(n4.x); fEc = h2f(n4.y);
            fOs = h2f(n4.z); fOc = h2f(n4.w);
            n4 = n42; lf = lf2; rg = rg2;
            idx += CW;
        }
    }
}

template <int PHASE>  // 0: x_img -> g_state ; 1: g_state -> out
__global__ void __launch_bounds__(NTHREADS, 2)
fused5_kernel(const float* __restrict__ x_img,
              const float* __restrict__ omega,
              const float* __restrict__ Kp,
              float* __restrict__ out) {
    extern __shared__ uint4 sm4[];
    uint4* bufA = sm4;
    uint4* bufB = sm4 + SMP;

    const int tid = threadIdx.x;
    const int t = tid % TCOLS;         // owns pixel cols 2t, 2t+1
    const int strip = tid / TCOLS;
    const int r0p = 1 + strip * PACKS_PER;
    const int b = blockIdx.y;
    const int y0 = blockIdx.x * TY;
    const int xe = 2 * t;
    const int ic = t + 1;              // own cell within row
    const float2* __restrict__ om2 = (const float2*)omega;

    const float DTK = DTc * Kp[0];
    SC C;
    C.DTK2 = pk2(DTK, DTK);
    C.ONE2 = pk2(1.0f, 1.0f);
    C.C3 = pk2(-1.0f / 6.0f, -1.0f / 6.0f);
    C.C2 = pk2(-0.5f, -0.5f);
    C.C4 = pk2(4.1666668e-2f, 4.1666668e-2f);
    SCH H;
    H.DTKh = fpair2h(DTK, DTK);
    H.ONEh = 0x3C003C00u;
    H.C3h = fpair2h(-1.0f / 6.0f, -1.0f / 6.0f);
    H.mHh = fpair2h(-0.5f, -0.5f);

    // Zero pad ring of both buffers (h2 zero bits = 0.0).
    const uint4 Z = make_uint4(0u, 0u, 0u, 0u);
    for (int i = tid; i < CW; i += NTHREADS) {
        bufA[i] = Z; bufA[(RPP - 1) * CW + i] = Z;
        bufB[i] = Z; bufB[(RPP - 1) * CW + i] = Z;
    }
    for (int r = 1 + tid; r < RPP - 1; r += NTHREADS) {
        bufA[r * CW] = Z; bufA[r * CW + CW - 1] = Z;
        bufB[r * CW] = Z; bufB[r * CW + CW - 1] = Z;
    }

    // Init state into bufA; out-of-image rows = exact 0.
#pragma unroll
    for (int j = 0; j < PACKS_PER; j++) {
        const int rp = r0p + j;
        const int gy0 = y0 - HALO + 2 * (rp - 1);
        const int gy1 = gy0 + 1;
        const bool in0 = (gy0 >= 0) && (gy0 < HH);
        const bool in1 = (gy1 >= 0) && (gy1 < HH);
        if (PHASE == 0) {
            float sE0 = 0.f, cE0 = 0.f, sO0 = 0.f, cO0 = 0.f;
            float sE1 = 0.f, cE1 = 0.f, sO1 = 0.f, cO1 = 0.f;
            if (in0) {
                float2 v = *(const float2*)&x_img[b * HW + gy0 * WW + xe];
                __sincosf(fmaf(2.0f * PIf, v.x, -PIf), &sE0, &cE0);
                __sincosf(fmaf(2.0f * PIf, v.y, -PIf), &sO0, &cO0);
            }
            if (in1) {
                float2 v = *(const float2*)&x_img[b * HW + gy1 * WW + xe];
                __sincosf(fmaf(2.0f * PIf, v.x, -PIf), &sE1, &cE1);
                __sincosf(fmaf(2.0f * PIf, v.y, -PIf), &sO1, &cO1);
            }
            bufA[rp * CW + ic] = make_uint4(fpair2h(sE0, sE1), fpair2h(cE0, cE1),
                                            fpair2h(sO0, sO1), fpair2h(cO0, cO1));
        } else {
            // fp16 in, fp16 cells out: pure PRMT repack, zero conversions.
            uint2 v0 = in0 ? g_state[(long)b * HW2 + gy0 * TCOLS + t] : make_uint2(0u, 0u);
            uint2 v1 = in1 ? g_state[(long)b * HW2 + gy1 * TCOLS + t] : make_uint2(0u, 0u);
            bufA[rp * CW + ic] = make_uint4(los16(v0.x, v1.x), los16(v0.y, v1.y),
                                            his16(v0.x, v1.x), his16(v0.y, v1.y));
        }
    }

    // Fold the omega flag (doubles as the post-init barrier).
    int pf = (tid < 64) ? g_parts[tid] : 0;
    const int flg = __syncthreads_or(pf);

    const int gybase = y0 - HALO + 2 * (r0p - 1);

    // Uniform branch: omega machinery compiled out of the hot path.
    if (flg)
        run_steps<PHASE, true>(bufA, bufB, r0p, ic, t, gybase, y0, b, xe, C, H, om2, out);
    else
        run_steps<PHASE, false>(bufA, bufB, r0p, ic, t, gybase, y0, b, xe, C, H, om2, out);
}

extern "C" void kernel_launch(void* const* d_in, const int* in_sizes, int n_in,
                              void* d_out, int out_size) {
    const float* x_img = (const float*)d_in[0];  // (B,1,H,W)
    const float* omega = (const float*)d_in[1];  // (1,1,H,W)
    const float* Kp    = (const float*)d_in[2];  // scalar
    float* out = (float*)d_out;

    static bool configured = false;
    if (!configured) {
        cudaFuncSetAttribute(fused5_kernel<0>,
                             cudaFuncAttributeMaxDynamicSharedMemorySize, SMEM_BYTES);
        cudaFuncSetAttribute(fused5_kernel<1>,
                             cudaFuncAttributeMaxDynamicSharedMemorySize, SMEM_BYTES);
        configured = true;
    }

    flag_kernel<<<64, 256>>>(omega);

    dim3 grid(TILES, BB);
    dim3 block(NTHREADS);
    fused5_kernel<0><<<grid, block, SMEM_BYTES>>>(x_img, omega, Kp, out);
    fused5_kernel<1><<<grid, block, SMEM_BYTES>>>(x_img, omega, Kp, out);
}